// round 2
// baseline (speedup 1.0000x reference)
#include <cuda_runtime.h>
#include <cstddef>

// ---------------------------------------------------------------------------
// Problem constants (shapes are fixed by the dataset)
// ---------------------------------------------------------------------------
#define NMAX   200000
#define EMB    128
#define ENC1   256
#define NEG_SLOPE 0.1f
#define LN_EPS 1e-5f

// ---------------------------------------------------------------------------
// Scratch (static __device__ arrays; no allocations allowed)
// ---------------------------------------------------------------------------
__device__ float g_H[4][(size_t)NMAX * EMB];   // h_list[0..3]
__device__ float g_XL[(size_t)NMAX * EMB];     // xl buffer
__device__ float g_AGG[(size_t)NMAX * EMB];    // aggregation buffer
__device__ float g_H1[(size_t)NMAX * ENC1];    // encoder intermediate
__device__ float g_degA[NMAX];
__device__ float g_degB[NMAX];
__device__ float g_disA[NMAX];
__device__ float g_disB[NMAX];
__device__ float g_invA[NMAX];
__device__ float g_invB[NMAX];

// ---------------------------------------------------------------------------
// Helpers
// ---------------------------------------------------------------------------
__device__ __forceinline__ float leaky(float v) {
    return v >= 0.0f ? v : NEG_SLOPE * v;
}
__device__ __forceinline__ float relu_(float v) { return fmaxf(v, 0.0f); }

// packed fp32x2 (Blackwell double-rate FFMA path)
__device__ __forceinline__ unsigned long long pack2(float x, float y) {
    unsigned long long r;
    asm("mov.b64 %0, {%1, %2};" : "=l"(r) : "f"(x), "f"(y));
    return r;
}
__device__ __forceinline__ unsigned long long fma2(unsigned long long a,
                                                   unsigned long long b,
                                                   unsigned long long c) {
    unsigned long long d;
    asm("fma.rn.f32x2 %0, %1, %2, %3;" : "=l"(d) : "l"(a), "l"(b), "l"(c));
    return d;
}
__device__ __forceinline__ void unpack2(unsigned long long v, float& x, float& y) {
    asm("mov.b64 {%0, %1}, %2;" : "=f"(x), "=f"(y) : "l"(v));
}

// ---------------------------------------------------------------------------
// Degree kernels
// ---------------------------------------------------------------------------
__global__ void deg_init_kernel(float* degA, float* degB, int n) {
    int i = blockIdx.x * blockDim.x + threadIdx.x;
    if (i < n) { degA[i] = 1.0f; degB[i] = 1.0f; }
}

__global__ void deg_count_kernel(const int* __restrict__ rows, float* deg, int E) {
    int e = blockIdx.x * blockDim.x + threadIdx.x;
    if (e < E) atomicAdd(&deg[rows[e]], 1.0f);
}

__global__ void deg_fin_kernel(const float* __restrict__ deg,
                               float* __restrict__ dis,
                               float* __restrict__ inv, int n) {
    int i = blockIdx.x * blockDim.x + threadIdx.x;
    if (i < n) {
        float d = deg[i];
        dis[i] = rsqrtf(d);
        inv[i] = 1.0f / d;
    }
}

// ---------------------------------------------------------------------------
// Encoder layer 1: [M,32] @ [32,256] + b, leaky. Warp-per-row.
// ---------------------------------------------------------------------------
__global__ void enc1_kernel(const float* __restrict__ x,
                            const float* __restrict__ W1,
                            const float* __restrict__ b1,
                            float* __restrict__ out, int M) {
    __shared__ float Ws[32 * ENC1];  // 32 KB
    int tid = threadIdx.x;
    for (int i = tid; i < 32 * ENC1 / 4; i += 256)
        ((float4*)Ws)[i] = ((const float4*)W1)[i];
    __syncthreads();

    int lane = tid & 31, warp = tid >> 5;
    int row = blockIdx.x * 8 + warp;
    if (row >= M) return;

    float xv = x[(size_t)row * 32 + lane];
    float acc0[4] = {0.f, 0.f, 0.f, 0.f};   // cols lane*4 .. +3
    float acc1[4] = {0.f, 0.f, 0.f, 0.f};   // cols 128 + lane*4 .. +3
#pragma unroll
    for (int k = 0; k < 32; k++) {
        float a = __shfl_sync(0xffffffffu, xv, k);
        float4 w0 = *(const float4*)(Ws + k * ENC1 + lane * 4);
        float4 w1 = *(const float4*)(Ws + k * ENC1 + 128 + lane * 4);
        acc0[0] += a * w0.x; acc0[1] += a * w0.y; acc0[2] += a * w0.z; acc0[3] += a * w0.w;
        acc1[0] += a * w1.x; acc1[1] += a * w1.y; acc1[2] += a * w1.z; acc1[3] += a * w1.w;
    }
    float4 bb0 = *(const float4*)(b1 + lane * 4);
    float4 bb1 = *(const float4*)(b1 + 128 + lane * 4);
    float4 o0, o1;
    o0.x = leaky(acc0[0] + bb0.x); o0.y = leaky(acc0[1] + bb0.y);
    o0.z = leaky(acc0[2] + bb0.z); o0.w = leaky(acc0[3] + bb0.w);
    o1.x = leaky(acc1[0] + bb1.x); o1.y = leaky(acc1[1] + bb1.y);
    o1.z = leaky(acc1[2] + bb1.z); o1.w = leaky(acc1[3] + bb1.w);
    *(float4*)(out + (size_t)row * ENC1 + lane * 4) = o0;
    *(float4*)(out + (size_t)row * ENC1 + 128 + lane * 4) = o1;
}

// ---------------------------------------------------------------------------
// Generic GEMM: out[M,128] = A[M,K] @ W[K,128] + bias, K multiple of 128.
// BM=64 rows/block, 256 threads. Uses packed fp32x2 FFMA.
// act: 0 = none, 1 = leaky
// ---------------------------------------------------------------------------
__global__ void gemm128_kernel(const float* __restrict__ A,
                               const float* __restrict__ W,
                               const float* __restrict__ bias,
                               float* __restrict__ out,
                               int M, int K, int act) {
    extern __shared__ float sm[];
    float* Ws = sm;              // 128*128 floats (64 KB)
    float* As = sm + 128 * 128;  // 64*128 floats (32 KB)

    const int tid = threadIdx.x;
    const int lane = tid & 31;
    const int warp = tid >> 5;
    const int row0 = blockIdx.x * 64;

    unsigned long long acc[8][2];
#pragma unroll
    for (int i = 0; i < 8; i++) { acc[i][0] = 0ull; acc[i][1] = 0ull; }

    for (int kk = 0; kk < K; kk += 128) {
        // stage W chunk [128 x 128]
        float4* Ws4 = (float4*)Ws;
#pragma unroll
        for (int i = 0; i < 16; i++) {
            int f4 = tid + i * 256;           // 0..4095
            int k = f4 >> 5;
            int n4 = f4 & 31;
            Ws4[f4] = *(const float4*)(W + (size_t)(kk + k) * 128 + n4 * 4);
        }
        // stage A chunk [64 x 128]
        float4* As4 = (float4*)As;
#pragma unroll
        for (int i = 0; i < 8; i++) {
            int f4 = tid + i * 256;           // 0..2047
            int r = f4 >> 5;
            int c4 = f4 & 31;
            int gr = row0 + r;
            float4 v = make_float4(0.f, 0.f, 0.f, 0.f);
            if (gr < M) v = *(const float4*)(A + (size_t)gr * K + kk + c4 * 4);
            As4[f4] = v;
        }
        __syncthreads();

#pragma unroll
        for (int k4 = 0; k4 < 32; k4++) {
            unsigned long long w01[4], w23[4];
#pragma unroll
            for (int s = 0; s < 4; s++) {
                float4 wv = ((const float4*)Ws)[(k4 * 4 + s) * 32 + lane];
                w01[s] = pack2(wv.x, wv.y);
                w23[s] = pack2(wv.z, wv.w);
            }
#pragma unroll
            for (int i = 0; i < 8; i++) {
                float4 av = ((const float4*)As)[(warp * 8 + i) * 32 + k4];
                unsigned long long aa;
                aa = pack2(av.x, av.x);
                acc[i][0] = fma2(aa, w01[0], acc[i][0]);
                acc[i][1] = fma2(aa, w23[0], acc[i][1]);
                aa = pack2(av.y, av.y);
                acc[i][0] = fma2(aa, w01[1], acc[i][0]);
                acc[i][1] = fma2(aa, w23[1], acc[i][1]);
                aa = pack2(av.z, av.z);
                acc[i][0] = fma2(aa, w01[2], acc[i][0]);
                acc[i][1] = fma2(aa, w23[2], acc[i][1]);
                aa = pack2(av.w, av.w);
                acc[i][0] = fma2(aa, w01[3], acc[i][0]);
                acc[i][1] = fma2(aa, w23[3], acc[i][1]);
            }
        }
        __syncthreads();
    }

    float4 bv = *(const float4*)(bias + lane * 4);
#pragma unroll
    for (int i = 0; i < 8; i++) {
        int gr = row0 + warp * 8 + i;
        if (gr >= M) break;
        float4 o;
        unpack2(acc[i][0], o.x, o.y);
        unpack2(acc[i][1], o.z, o.w);
        o.x += bv.x; o.y += bv.y; o.z += bv.z; o.w += bv.w;
        if (act == 1) {
            o.x = leaky(o.x); o.y = leaky(o.y); o.z = leaky(o.z); o.w = leaky(o.w);
        }
        *(float4*)(out + (size_t)gr * 128 + lane * 4) = o;
    }
}

// ---------------------------------------------------------------------------
// GCN self-loop term: agg[i,:] = relu(xl[i,:] + root) * invdeg[i]
// One thread per float4. n4 = N*32.
// ---------------------------------------------------------------------------
__global__ void gcn_self_kernel(const float* __restrict__ xl,
                                const float* __restrict__ root,
                                const float* __restrict__ invdeg,
                                float* __restrict__ agg, int n4) {
    int idx = blockIdx.x * blockDim.x + threadIdx.x;
    if (idx >= n4) return;
    int row = idx >> 5;
    int c4 = idx & 31;
    float4 v = ((const float4*)xl)[idx];
    float4 r = ((const float4*)root)[c4];
    float id = invdeg[row];
    float4 o;
    o.x = relu_(v.x + r.x) * id;
    o.y = relu_(v.y + r.y) * id;
    o.z = relu_(v.z + r.z) * id;
    o.w = relu_(v.w + r.w) * id;
    ((float4*)agg)[idx] = o;
}

// ---------------------------------------------------------------------------
// Edge scatter: agg[col,:] += dis[row]*dis[col] * relu(xl[row,:])
// Warp per edge, vector atomics (red.global.add.v4.f32).
// ---------------------------------------------------------------------------
__global__ void gcn_scatter_kernel(const int* __restrict__ rows,
                                   const int* __restrict__ cols,
                                   const float* __restrict__ dis,
                                   const float* __restrict__ xl,
                                   float* __restrict__ agg, int E) {
    int e = blockIdx.x * 8 + (threadIdx.x >> 5);
    if (e >= E) return;
    int lane = threadIdx.x & 31;
    int r = __ldg(rows + e);
    int c = __ldg(cols + e);
    float nrm = __ldg(dis + r) * __ldg(dis + c);
    float4 v = *(const float4*)(xl + (size_t)r * EMB + lane * 4);
    v.x = relu_(v.x) * nrm;
    v.y = relu_(v.y) * nrm;
    v.z = relu_(v.z) * nrm;
    v.w = relu_(v.w) * nrm;
    float* p = agg + (size_t)c * EMB + lane * 4;
    asm volatile("red.global.add.v4.f32 [%0], {%1, %2, %3, %4};"
                 :: "l"(p), "f"(v.x), "f"(v.y), "f"(v.z), "f"(v.w)
                 : "memory");
}

// ---------------------------------------------------------------------------
// LayerNorm + LeakyReLU + residual: hnext = leaky(LN(agg)*g + b) + hprev
// Warp per row.
// ---------------------------------------------------------------------------
__global__ void ln_res_kernel(const float* __restrict__ agg,
                              const float* __restrict__ g,
                              const float* __restrict__ b,
                              const float* __restrict__ hprev,
                              float* __restrict__ hnext, int M) {
    int lane = threadIdx.x & 31;
    int warp = threadIdx.x >> 5;
    int row = blockIdx.x * 8 + warp;
    if (row >= M) return;

    float4 v = ((const float4*)agg)[(size_t)row * 32 + lane];
    float s = v.x + v.y + v.z + v.w;
#pragma unroll
    for (int off = 16; off > 0; off >>= 1) s += __shfl_xor_sync(0xffffffffu, s, off);
    float mu = s * (1.0f / 128.0f);

    float dx = v.x - mu, dy = v.y - mu, dz = v.z - mu, dw = v.w - mu;
    float q = dx * dx + dy * dy + dz * dz + dw * dw;
#pragma unroll
    for (int off = 16; off > 0; off >>= 1) q += __shfl_xor_sync(0xffffffffu, q, off);
    float rstd = rsqrtf(q * (1.0f / 128.0f) + LN_EPS);

    float4 gg = ((const float4*)g)[lane];
    float4 bb = ((const float4*)b)[lane];
    float4 hp = ((const float4*)hprev)[(size_t)row * 32 + lane];
    float4 o;
    o.x = leaky(dx * rstd * gg.x + bb.x) + hp.x;
    o.y = leaky(dy * rstd * gg.y + bb.y) + hp.y;
    o.z = leaky(dz * rstd * gg.z + bb.z) + hp.z;
    o.w = leaky(dw * rstd * gg.w + bb.w) + hp.w;
    ((float4*)hnext)[(size_t)row * 32 + lane] = o;
}

// ---------------------------------------------------------------------------
// JK-concat output: out[i, l*128 + j] = H[l][i, j], i < rows
// One thread per output float4.
// ---------------------------------------------------------------------------
__global__ void concat_kernel(const float* __restrict__ h0,
                              const float* __restrict__ h1,
                              const float* __restrict__ h2,
                              const float* __restrict__ h3,
                              float* __restrict__ out, int rows) {
    int idx = blockIdx.x * blockDim.x + threadIdx.x;   // float4 index over rows*128
    if (idx >= rows * 128) return;
    int row = idx >> 7;
    int c = idx & 127;
    int l = c >> 5;
    int j = c & 31;
    const float* h = (l == 0) ? h0 : (l == 1) ? h1 : (l == 2) ? h2 : h3;
    ((float4*)out)[idx] = ((const float4*)h)[(size_t)row * 32 + j];
}

// ---------------------------------------------------------------------------
// Launch
// ---------------------------------------------------------------------------
extern "C" void kernel_launch(void* const* d_in, const int* in_sizes, int n_in,
                              void* d_out, int out_size) {
    const float* x        = (const float*)d_in[0];
    const float* enc_w1   = (const float*)d_in[1];
    const float* enc_b1   = (const float*)d_in[2];
    const float* enc_w2   = (const float*)d_in[3];
    const float* enc_b2   = (const float*)d_in[4];
    const float* conv_w   = (const float*)d_in[5];
    const float* conv_b   = (const float*)d_in[6];
    const float* conv_rt  = (const float*)d_in[7];
    const float* reconv_w = (const float*)d_in[8];
    const float* reconv_b = (const float*)d_in[9];
    const float* reconv_rt= (const float*)d_in[10];
    const float* ln_g     = (const float*)d_in[11];
    const float* ln_b     = (const float*)d_in[12];
    const int*   eA       = (const int*)d_in[13];
    const int*   eB       = (const int*)d_in[14];

    const int N  = in_sizes[0] / 32;
    const int Ea = in_sizes[13] / 2;
    const int Eb = in_sizes[14] / 2;
    const int rows_out = out_size / 512;

    const int* rowsA = eA;       const int* colsA = eA + Ea;
    const int* rowsB = eB;       const int* colsB = eB + Eb;

    void* p;
    cudaGetSymbolAddress(&p, g_H);    float* H    = (float*)p;
    cudaGetSymbolAddress(&p, g_XL);   float* XL   = (float*)p;
    cudaGetSymbolAddress(&p, g_AGG);  float* AGG  = (float*)p;
    cudaGetSymbolAddress(&p, g_H1);   float* H1E  = (float*)p;
    cudaGetSymbolAddress(&p, g_degA); float* degA = (float*)p;
    cudaGetSymbolAddress(&p, g_degB); float* degB = (float*)p;
    cudaGetSymbolAddress(&p, g_disA); float* disA = (float*)p;
    cudaGetSymbolAddress(&p, g_disB); float* disB = (float*)p;
    cudaGetSymbolAddress(&p, g_invA); float* invA = (float*)p;
    cudaGetSymbolAddress(&p, g_invB); float* invB = (float*)p;

    const size_t hstride = (size_t)NMAX * EMB;

    const int SMEM_GEMM = (128 * 128 + 64 * 128) * 4;  // 96 KB
    cudaFuncSetAttribute(gemm128_kernel, cudaFuncAttributeMaxDynamicSharedMemorySize,
                         SMEM_GEMM);

    // degrees
    deg_init_kernel<<<(N + 255) / 256, 256>>>(degA, degB, N);
    deg_count_kernel<<<(Ea + 255) / 256, 256>>>(rowsA, degA, Ea);
    deg_count_kernel<<<(Eb + 255) / 256, 256>>>(rowsB, degB, Eb);
    deg_fin_kernel<<<(N + 255) / 256, 256>>>(degA, disA, invA, N);
    deg_fin_kernel<<<(N + 255) / 256, 256>>>(degB, disB, invB, N);

    // encoder
    enc1_kernel<<<(N + 7) / 8, 256>>>(x, enc_w1, enc_b1, H1E, N);
    gemm128_kernel<<<(N + 63) / 64, 256, SMEM_GEMM>>>(H1E, enc_w2, enc_b2,
                                                      H /* H0 */, N, ENC1, 1);

    const int n4 = N * 32;
    for (int l = 0; l < 3; l++) {
        const float* hl = H + (size_t)l * hstride;
        float* hn = H + (size_t)(l + 1) * hstride;

        // conv (node->net edges)
        gemm128_kernel<<<(N + 63) / 64, 256, SMEM_GEMM>>>(
            hl, conv_w + (size_t)l * EMB * EMB, conv_b + l * EMB, XL, N, EMB, 0);
        gcn_self_kernel<<<(n4 + 255) / 256, 256>>>(XL, conv_rt + l * EMB, invA, AGG, n4);
        gcn_scatter_kernel<<<(Ea + 7) / 8, 256>>>(rowsA, colsA, disA, XL, AGG, Ea);

        // reconv (net->node edges)
        gemm128_kernel<<<(N + 63) / 64, 256, SMEM_GEMM>>>(
            AGG, reconv_w + (size_t)l * EMB * EMB, reconv_b + l * EMB, XL, N, EMB, 0);
        gcn_self_kernel<<<(n4 + 255) / 256, 256>>>(XL, reconv_rt + l * EMB, invB, AGG, n4);
        gcn_scatter_kernel<<<(Eb + 7) / 8, 256>>>(rowsB, colsB, disB, XL, AGG, Eb);

        // LN + leaky + residual
        ln_res_kernel<<<(N + 7) / 8, 256>>>(AGG, ln_g + l * EMB, ln_b + l * EMB,
                                            hl, hn, N);
    }

    // concat output
    concat_kernel<<<(rows_out * 128 + 255) / 256, 256>>>(
        H, H + hstride, H + 2 * hstride, H + 3 * hstride, (float*)d_out, rows_out);
}

// round 5
// speedup vs baseline: 1.5367x; 1.5367x over previous
#include <cuda_runtime.h>
#include <cuda_bf16.h>
#include <cstddef>
#include <cstdint>

// ---------------------------------------------------------------------------
// Problem constants
// ---------------------------------------------------------------------------
#define NMAX   200000
#define EMB    128
#define ENC1   256
#define NEG_SLOPE 0.1f
#define LN_EPS 1e-5f

// ---------------------------------------------------------------------------
// Scratch (static __device__ arrays; no allocations allowed)
// ---------------------------------------------------------------------------
__device__ float g_H[4][(size_t)NMAX * EMB];   // h_list[0..3]
__device__ float g_XL[(size_t)NMAX * EMB];     // xl buffer
__device__ float g_AGG[(size_t)NMAX * EMB];    // aggregation buffer
__device__ float g_H1[(size_t)NMAX * ENC1];    // encoder intermediate
__device__ float g_degA[NMAX];
__device__ float g_degB[NMAX];
__device__ float g_disA[NMAX];
__device__ float g_disB[NMAX];
__device__ float g_invA[NMAX];
__device__ float g_invB[NMAX];
// Prepped weight chunks: 18 chunks of [128 n-rows x 64 k-cols] bf16,
// XOR-swizzled (same layout the GEMM uses in SMEM). hi/lo split.
//  chunk 0,1   : enc_w1 (n halves 0,128), K=32 (padded)
//  chunk 2..5  : enc_w2 k0 = 0,64,128,192
//  chunk 6+2l  : conv_w[l] k0 = 0,64
//  chunk 12+2l : reconv_w[l] k0 = 0,64
__device__ __nv_bfloat16 g_Bhi[18 * 8192];
__device__ __nv_bfloat16 g_Blo[18 * 8192];

// ---------------------------------------------------------------------------
// Helpers
// ---------------------------------------------------------------------------
__device__ __forceinline__ float leaky(float v) {
    return v >= 0.0f ? v : NEG_SLOPE * v;
}
__device__ __forceinline__ float relu_(float v) { return fmaxf(v, 0.0f); }

__device__ __forceinline__ uint32_t smem_u32(const void* p) {
    uint32_t a;
    asm("{ .reg .u64 t; cvta.to.shared.u64 t, %1; cvt.u32.u64 %0, t; }"
        : "=r"(a) : "l"(p));
    return a;
}

__device__ __forceinline__ void ldsm4(uint32_t* r, uint32_t addr) {
    asm volatile("ldmatrix.sync.aligned.m8n8.x4.shared.b16 {%0,%1,%2,%3}, [%4];"
                 : "=r"(r[0]), "=r"(r[1]), "=r"(r[2]), "=r"(r[3]) : "r"(addr));
}

__device__ __forceinline__ void mma16816(float* c, const uint32_t* a,
                                         uint32_t b0, uint32_t b1) {
    asm volatile(
        "mma.sync.aligned.m16n8k16.row.col.f32.bf16.bf16.f32 "
        "{%0,%1,%2,%3}, {%4,%5,%6,%7}, {%8,%9}, {%0,%1,%2,%3};"
        : "+f"(c[0]), "+f"(c[1]), "+f"(c[2]), "+f"(c[3])
        : "r"(a[0]), "r"(a[1]), "r"(a[2]), "r"(a[3]), "r"(b0), "r"(b1));
}

// ---------------------------------------------------------------------------
// Degree kernels
// ---------------------------------------------------------------------------
__global__ void deg_init_kernel(float* degA, float* degB, int n) {
    int i = blockIdx.x * blockDim.x + threadIdx.x;
    if (i < n) { degA[i] = 1.0f; degB[i] = 1.0f; }
}

__global__ void deg_count_kernel(const int* __restrict__ rows, float* deg, int E) {
    int e = blockIdx.x * blockDim.x + threadIdx.x;
    if (e < E) atomicAdd(&deg[rows[e]], 1.0f);
}

__global__ void deg_fin_kernel(const float* __restrict__ deg,
                               float* __restrict__ dis,
                               float* __restrict__ inv, int n) {
    int i = blockIdx.x * blockDim.x + threadIdx.x;
    if (i < n) {
        float d = deg[i];
        dis[i] = rsqrtf(d);
        inv[i] = 1.0f / d;
    }
}

// ---------------------------------------------------------------------------
// Weight prep: one 128(n) x 64(k) chunk -> swizzled bf16 hi/lo.
// W is row-major [K x ldn]; chunk covers W[k0 .. k0+kcount), cols n0..n0+128.
// Swizzle: byte_off = n*128 + ((k*2) ^ ((n&7)<<4))
// ---------------------------------------------------------------------------
__global__ void prep_w_kernel(const float* __restrict__ W, int ldn, int k0, int n0,
                              int kcount,
                              __nv_bfloat16* __restrict__ bh,
                              __nv_bfloat16* __restrict__ bl) {
    int idx = blockIdx.x * blockDim.x + threadIdx.x;
    if (idx >= 128 * 64) return;
    int n = idx >> 6;
    int k = idx & 63;
    float v = (k < kcount) ? W[(size_t)(k0 + k) * ldn + n0 + n] : 0.0f;
    __nv_bfloat16 h = __float2bfloat16(v);
    __nv_bfloat16 l = __float2bfloat16(v - __bfloat162float(h));
    int off = n * 128 + ((k * 2) ^ ((n & 7) << 4));
    bh[off >> 1] = h;
    bl[off >> 1] = l;
}

// ---------------------------------------------------------------------------
// Tensor-core GEMM (mma.sync bf16 3-split): out[M,128] = A[M,KV] @ W + bias
//   mode 0: out[gr*ostride + colofs + n] = leaky(d + bias[n])
//   mode 1: xl = d + bias[n]; out[gr*128+n] = xl;
//           agg[gr*128+n] = relu(xl + root[n]) * invdeg[gr]
// Block: 128 rows x 128 cols, 8 warps (warp = 32 rows x 64 cols).
// ---------------------------------------------------------------------------
#define SM_A_HI 0
#define SM_A_LO 16384
#define SM_B_HI 32768
#define SM_B_LO 49152
#define SMEM_TC 65536

__global__ void __launch_bounds__(256, 2)
gemm_tc_kernel(const float* __restrict__ A, int lda, int M,
               const __nv_bfloat16* __restrict__ BhiG,
               const __nv_bfloat16* __restrict__ BloG,
               int kchunks, int KV,
               const float* __restrict__ bias,
               float* __restrict__ out, int ostride, int colofs,
               int mode,
               const float* __restrict__ root,
               const float* __restrict__ invdeg,
               float* __restrict__ agg) {
    extern __shared__ char sm[];
    const uint32_t sb = smem_u32(sm);
    const int tid = threadIdx.x;
    const int w = tid >> 5;
    const int lane = tid & 31;
    const int wm = w & 3;          // m-block (32 rows)
    const int wn = w >> 2;         // n-half (64 cols)
    const int row0 = blockIdx.x * 128;

    float acc[2][8][4];
#pragma unroll
    for (int a = 0; a < 2; a++)
#pragma unroll
        for (int b = 0; b < 8; b++)
#pragma unroll
            for (int c = 0; c < 4; c++) acc[a][b][c] = 0.0f;

    for (int ck = 0; ck < kchunks; ck++) {
        const int kbase = ck * 64;
        int kcols = KV - kbase; if (kcols > 64) kcols = 64;
        const int ksteps = (kcols + 15) >> 4;

        // ---- stage B chunk (pre-swizzled in global): 2 x 16KB raw copy ----
        {
            const float4* sh = (const float4*)(BhiG + (size_t)ck * 8192);
            const float4* sl = (const float4*)(BloG + (size_t)ck * 8192);
            float4* dh = (float4*)(sm + SM_B_HI);
            float4* dl = (float4*)(sm + SM_B_LO);
            for (int i = tid; i < 1024; i += 256) { dh[i] = sh[i]; dl[i] = sl[i]; }
        }

        // ---- stage A chunk [128 rows x 64 cols] fp32 -> bf16 hi/lo ----
#pragma unroll
        for (int i = 0; i < 8; i++) {
            const int idx = tid + i * 256;        // 0..2047 float4s
            const int r = idx >> 4;
            const int c4 = idx & 15;
            float4 v = make_float4(0.f, 0.f, 0.f, 0.f);
            const int gr = row0 + r;
            if (gr < M && c4 * 4 < kcols)
                v = *(const float4*)(A + (size_t)gr * lda + kbase + c4 * 4);
            __nv_bfloat16 hx = __float2bfloat16(v.x);
            __nv_bfloat16 hy = __float2bfloat16(v.y);
            __nv_bfloat16 hz = __float2bfloat16(v.z);
            __nv_bfloat16 hw = __float2bfloat16(v.w);
            __nv_bfloat16 lx = __float2bfloat16(v.x - __bfloat162float(hx));
            __nv_bfloat16 ly = __float2bfloat16(v.y - __bfloat162float(hy));
            __nv_bfloat16 lz = __float2bfloat16(v.z - __bfloat162float(hz));
            __nv_bfloat16 lw = __float2bfloat16(v.w - __bfloat162float(hw));
            uint32_t hi01 = ((uint32_t)__bfloat16_as_ushort(hy) << 16) |
                             (uint32_t)__bfloat16_as_ushort(hx);
            uint32_t hi23 = ((uint32_t)__bfloat16_as_ushort(hw) << 16) |
                             (uint32_t)__bfloat16_as_ushort(hz);
            uint32_t lo01 = ((uint32_t)__bfloat16_as_ushort(ly) << 16) |
                             (uint32_t)__bfloat16_as_ushort(lx);
            uint32_t lo23 = ((uint32_t)__bfloat16_as_ushort(lw) << 16) |
                             (uint32_t)__bfloat16_as_ushort(lz);
            // byte offset with XOR swizzle (8-byte unit stays contiguous)
            int off = r * 128 + ((c4 * 8) ^ ((r & 7) << 4));
            *(uint2*)(sm + SM_A_HI + off) = make_uint2(hi01, hi23);
            *(uint2*)(sm + SM_A_LO + off) = make_uint2(lo01, lo23);
        }
        __syncthreads();

        // ---- compute ----
        for (int ks = 0; ks < ksteps; ks++) {
            // A fragments: 2 m-tiles (16 rows each), hi + lo
            uint32_t ah[2][4], al[2][4];
            {
                const int rr = (lane & 15);
                const int colb = ks * 32 + (lane & 16);
#pragma unroll
                for (int mt = 0; mt < 2; mt++) {
                    const int row = wm * 32 + mt * 16 + rr;
                    const uint32_t ad = (uint32_t)(row * 128 +
                                       (colb ^ ((row & 7) << 4)));
                    ldsm4(ah[mt], sb + SM_A_HI + ad);
                    ldsm4(al[mt], sb + SM_A_LO + ad);
                }
            }
            // loop over 4 n-pairs (16 cols each)
#pragma unroll
            for (int np = 0; np < 4; np++) {
                const int nb = wn * 64 + np * 16;
                const int n = nb + (lane & 7) + ((lane & 16) >> 1);
                const int colb = ks * 32 + ((lane & 8) << 1);
                const uint32_t bd = (uint32_t)(n * 128 +
                                   (colb ^ ((n & 7) << 4)));
                uint32_t bh[4], bl[4];
                ldsm4(bh, sb + SM_B_HI + bd);
                ldsm4(bl, sb + SM_B_LO + bd);
#pragma unroll
                for (int mt = 0; mt < 2; mt++) {
#pragma unroll
                    for (int nt = 0; nt < 2; nt++) {
                        float* c = acc[mt][np * 2 + nt];
                        mma16816(c, ah[mt], bh[nt * 2], bh[nt * 2 + 1]);
                        mma16816(c, ah[mt], bl[nt * 2], bl[nt * 2 + 1]);
                        mma16816(c, al[mt], bh[nt * 2], bh[nt * 2 + 1]);
                    }
                }
            }
        }
        __syncthreads();
    }

    // ---- epilogue ----
    const int quad = lane >> 2;
    const int tq = lane & 3;
#pragma unroll
    for (int mt = 0; mt < 2; mt++) {
#pragma unroll
        for (int half = 0; half < 2; half++) {
            const int gr = row0 + wm * 32 + mt * 16 + half * 8 + quad;
            if (gr >= M) continue;
            if (mode == 0) {
                float* po = out + (size_t)gr * ostride + colofs + wn * 64;
#pragma unroll
                for (int j = 0; j < 8; j++) {
                    const int col = j * 8 + tq * 2;
                    float c0 = acc[mt][j][half * 2 + 0];
                    float c1 = acc[mt][j][half * 2 + 1];
                    float2 o;
                    o.x = leaky(c0 + __ldg(bias + wn * 64 + col));
                    o.y = leaky(c1 + __ldg(bias + wn * 64 + col + 1));
                    *(float2*)(po + col) = o;
                }
            } else {
                const float id = __ldg(invdeg + gr);
                float* px = out + (size_t)gr * 128 + wn * 64;
                float* pa = agg + (size_t)gr * 128 + wn * 64;
#pragma unroll
                for (int j = 0; j < 8; j++) {
                    const int col = j * 8 + tq * 2;
                    float xl0 = acc[mt][j][half * 2 + 0] + __ldg(bias + wn * 64 + col);
                    float xl1 = acc[mt][j][half * 2 + 1] + __ldg(bias + wn * 64 + col + 1);
                    float2 xv = make_float2(xl0, xl1);
                    float2 av;
                    av.x = relu_(xl0 + __ldg(root + wn * 64 + col)) * id;
                    av.y = relu_(xl1 + __ldg(root + wn * 64 + col + 1)) * id;
                    *(float2*)(px + col) = xv;
                    *(float2*)(pa + col) = av;
                }
            }
        }
    }
}

// ---------------------------------------------------------------------------
// Edge scatter: agg[col,:] += dis[row]*dis[col] * relu(xl[row,:])
// ---------------------------------------------------------------------------
__global__ void gcn_scatter_kernel(const int* __restrict__ rows,
                                   const int* __restrict__ cols,
                                   const float* __restrict__ dis,
                                   const float* __restrict__ xl,
                                   float* __restrict__ agg, int E) {
    int e = blockIdx.x * 8 + (threadIdx.x >> 5);
    if (e >= E) return;
    int lane = threadIdx.x & 31;
    int r = __ldg(rows + e);
    int c = __ldg(cols + e);
    float nrm = __ldg(dis + r) * __ldg(dis + c);
    float4 v = *(const float4*)(xl + (size_t)r * EMB + lane * 4);
    v.x = relu_(v.x) * nrm;
    v.y = relu_(v.y) * nrm;
    v.z = relu_(v.z) * nrm;
    v.w = relu_(v.w) * nrm;
    float* p = agg + (size_t)c * EMB + lane * 4;
    asm volatile("red.global.add.v4.f32 [%0], {%1, %2, %3, %4};"
                 :: "l"(p), "f"(v.x), "f"(v.y), "f"(v.z), "f"(v.w)
                 : "memory");
}

// ---------------------------------------------------------------------------
// LayerNorm + LeakyReLU + residual
// ---------------------------------------------------------------------------
__global__ void ln_res_kernel(const float* __restrict__ agg,
                              const float* __restrict__ g,
                              const float* __restrict__ b,
                              const float* __restrict__ hprev,
                              float* __restrict__ hnext, int M) {
    int lane = threadIdx.x & 31;
    int warp = threadIdx.x >> 5;
    int row = blockIdx.x * 8 + warp;
    if (row >= M) return;

    float4 v = ((const float4*)agg)[(size_t)row * 32 + lane];
    float s = v.x + v.y + v.z + v.w;
#pragma unroll
    for (int off = 16; off > 0; off >>= 1) s += __shfl_xor_sync(0xffffffffu, s, off);
    float mu = s * (1.0f / 128.0f);

    float dx = v.x - mu, dy = v.y - mu, dz = v.z - mu, dw = v.w - mu;
    float q = dx * dx + dy * dy + dz * dz + dw * dw;
#pragma unroll
    for (int off = 16; off > 0; off >>= 1) q += __shfl_xor_sync(0xffffffffu, q, off);
    float rstd = rsqrtf(q * (1.0f / 128.0f) + LN_EPS);

    float4 gg = ((const float4*)g)[lane];
    float4 bb = ((const float4*)b)[lane];
    float4 hp = ((const float4*)hprev)[(size_t)row * 32 + lane];
    float4 o;
    o.x = leaky(dx * rstd * gg.x + bb.x) + hp.x;
    o.y = leaky(dy * rstd * gg.y + bb.y) + hp.y;
    o.z = leaky(dz * rstd * gg.z + bb.z) + hp.z;
    o.w = leaky(dw * rstd * gg.w + bb.w) + hp.w;
    ((float4*)hnext)[(size_t)row * 32 + lane] = o;
}

// ---------------------------------------------------------------------------
// JK-concat output
// ---------------------------------------------------------------------------
__global__ void concat_kernel(const float* __restrict__ h0,
                              const float* __restrict__ h1,
                              const float* __restrict__ h2,
                              const float* __restrict__ h3,
                              float* __restrict__ out, int rows) {
    int idx = blockIdx.x * blockDim.x + threadIdx.x;
    if (idx >= rows * 128) return;
    int row = idx >> 7;
    int c = idx & 127;
    int l = c >> 5;
    int j = c & 31;
    const float* h = (l == 0) ? h0 : (l == 1) ? h1 : (l == 2) ? h2 : h3;
    ((float4*)out)[idx] = ((const float4*)h)[(size_t)row * 32 + j];
}

// ---------------------------------------------------------------------------
// Launch
// ---------------------------------------------------------------------------
extern "C" void kernel_launch(void* const* d_in, const int* in_sizes, int n_in,
                              void* d_out, int out_size) {
    const float* x        = (const float*)d_in[0];
    const float* enc_w1   = (const float*)d_in[1];
    const float* enc_b1   = (const float*)d_in[2];
    const float* enc_w2   = (const float*)d_in[3];
    const float* enc_b2   = (const float*)d_in[4];
    const float* conv_w   = (const float*)d_in[5];
    const float* conv_b   = (const float*)d_in[6];
    const float* conv_rt  = (const float*)d_in[7];
    const float* reconv_w = (const float*)d_in[8];
    const float* reconv_b = (const float*)d_in[9];
    const float* reconv_rt= (const float*)d_in[10];
    const float* ln_g     = (const float*)d_in[11];
    const float* ln_b     = (const float*)d_in[12];
    const int*   eA       = (const int*)d_in[13];
    const int*   eB       = (const int*)d_in[14];

    const int N  = in_sizes[0] / 32;
    const int Ea = in_sizes[13] / 2;
    const int Eb = in_sizes[14] / 2;
    const int rows_out = out_size / 512;

    const int* rowsA = eA; const int* colsA = eA + Ea;
    const int* rowsB = eB; const int* colsB = eB + Eb;

    void* p;
    cudaGetSymbolAddress(&p, g_H);    float* H    = (float*)p;
    cudaGetSymbolAddress(&p, g_XL);   float* XL   = (float*)p;
    cudaGetSymbolAddress(&p, g_AGG);  float* AGG  = (float*)p;
    cudaGetSymbolAddress(&p, g_H1);   float* H1E  = (float*)p;
    cudaGetSymbolAddress(&p, g_degA); float* degA = (float*)p;
    cudaGetSymbolAddress(&p, g_degB); float* degB = (float*)p;
    cudaGetSymbolAddress(&p, g_disA); float* disA = (float*)p;
    cudaGetSymbolAddress(&p, g_disB); float* disB = (float*)p;
    cudaGetSymbolAddress(&p, g_invA); float* invA = (float*)p;
    cudaGetSymbolAddress(&p, g_invB); float* invB = (float*)p;
    cudaGetSymbolAddress(&p, g_Bhi);  __nv_bfloat16* BH = (__nv_bfloat16*)p;
    cudaGetSymbolAddress(&p, g_Blo);  __nv_bfloat16* BL = (__nv_bfloat16*)p;

    const size_t hstride = (size_t)NMAX * EMB;

    cudaFuncSetAttribute(gemm_tc_kernel,
                         cudaFuncAttributeMaxDynamicSharedMemorySize, SMEM_TC);

    // ---- weight prep: 18 chunks ----
    // enc_w1 [32,256]: chunks 0,1 (n halves), kcount=32
    prep_w_kernel<<<32, 256>>>(enc_w1, 256, 0, 0,   32, BH + 0 * 8192, BL + 0 * 8192);
    prep_w_kernel<<<32, 256>>>(enc_w1, 256, 0, 128, 32, BH + 1 * 8192, BL + 1 * 8192);
    // enc_w2 [256,128]: chunks 2..5
    for (int c = 0; c < 4; c++)
        prep_w_kernel<<<32, 256>>>(enc_w2, 128, c * 64, 0, 64,
                                   BH + (2 + c) * 8192, BL + (2 + c) * 8192);
    for (int l = 0; l < 3; l++) {
        for (int c = 0; c < 2; c++) {
            prep_w_kernel<<<32, 256>>>(conv_w + (size_t)l * 16384, 128, c * 64, 0, 64,
                                       BH + (6 + 2 * l + c) * 8192,
                                       BL + (6 + 2 * l + c) * 8192);
            prep_w_kernel<<<32, 256>>>(reconv_w + (size_t)l * 16384, 128, c * 64, 0, 64,
                                       BH + (12 + 2 * l + c) * 8192,
                                       BL + (12 + 2 * l + c) * 8192);
        }
    }

    // ---- degrees ----
    deg_init_kernel<<<(N + 255) / 256, 256>>>(degA, degB, N);
    deg_count_kernel<<<(Ea + 255) / 256, 256>>>(rowsA, degA, Ea);
    deg_count_kernel<<<(Eb + 255) / 256, 256>>>(rowsB, degB, Eb);
    deg_fin_kernel<<<(N + 255) / 256, 256>>>(degA, disA, invA, N);
    deg_fin_kernel<<<(N + 255) / 256, 256>>>(degB, disB, invB, N);

    const int tiles = (N + 127) / 128;

    // ---- encoder ----
    gemm_tc_kernel<<<tiles, 256, SMEM_TC>>>(x, 32, N,
        BH + 0 * 8192, BL + 0 * 8192, 1, 32, enc_b1,
        H1E, 256, 0, 0, nullptr, nullptr, nullptr);
    gemm_tc_kernel<<<tiles, 256, SMEM_TC>>>(x, 32, N,
        BH + 1 * 8192, BL + 1 * 8192, 1, 32, enc_b1 + 128,
        H1E, 256, 128, 0, nullptr, nullptr, nullptr);
    gemm_tc_kernel<<<tiles, 256, SMEM_TC>>>(H1E, 256, N,
        BH + 2 * 8192, BL + 2 * 8192, 4, 256, enc_b2,
        H, 128, 0, 0, nullptr, nullptr, nullptr);

    // ---- GCN layers ----
    for (int l = 0; l < 3; l++) {
        const float* hl = H + (size_t)l * hstride;
        float* hn = H + (size_t)(l + 1) * hstride;

        gemm_tc_kernel<<<tiles, 256, SMEM_TC>>>(hl, 128, N,
            BH + (6 + 2 * l) * 8192, BL + (6 + 2 * l) * 8192, 2, 128,
            conv_b + l * EMB, XL, 128, 0, 1, conv_rt + l * EMB, invA, AGG);
        gcn_scatter_kernel<<<(Ea + 7) / 8, 256>>>(rowsA, colsA, disA, XL, AGG, Ea);

        gemm_tc_kernel<<<tiles, 256, SMEM_TC>>>(AGG, 128, N,
            BH + (12 + 2 * l) * 8192, BL + (12 + 2 * l) * 8192, 2, 128,
            reconv_b + l * EMB, XL, 128, 0, 1, reconv_rt + l * EMB, invB, AGG);
        gcn_scatter_kernel<<<(Eb + 7) / 8, 256>>>(rowsB, colsB, disB, XL, AGG, Eb);

        ln_res_kernel<<<(N + 7) / 8, 256>>>(AGG, ln_g + l * EMB, ln_b + l * EMB,
                                            hl, hn, N);
    }

    // ---- concat output ----
    concat_kernel<<<(rows_out * 128 + 255) / 256, 256>>>(
        H, H + hstride, H + 2 * hstride, H + 3 * hstride, (float*)d_out, rows_out);
}

// round 9
// speedup vs baseline: 1.6843x; 1.0961x over previous
#include <cuda_runtime.h>
#include <cuda_bf16.h>
#include <cstddef>
#include <cstdint>

// ---------------------------------------------------------------------------
// Problem constants
// ---------------------------------------------------------------------------
#define NMAX   200000
#define EMAX   650000
#define EMB    128
#define ENC1   256
#define NEG_SLOPE 0.1f
#define LN_EPS 1e-5f

// ---------------------------------------------------------------------------
// Scratch (static __device__ arrays; no allocations allowed)
// ---------------------------------------------------------------------------
__device__ float g_H[4][(size_t)NMAX * EMB];   // h_list[0..3]
__device__ float g_XL[(size_t)NMAX * EMB];     // xl buffer
__device__ float g_AGG[(size_t)NMAX * EMB];    // aggregation buffer
__device__ float g_H1[(size_t)NMAX * ENC1];    // encoder intermediate
__device__ float g_disA[NMAX];
__device__ float g_disB[NMAX];
__device__ float g_invA[NMAX];
__device__ float g_invB[NMAX];
// CSR scratch: [0,N) rowcntA | [N,2N) rowcntB | [2N,4N) colcnt (A then B)
//              [4N,6N) cursors (A then B)
__device__ int g_icsr[6 * NMAX];
__device__ int g_offs[2 * NMAX];       // scanned colcnt (concatenated A,B)
__device__ int g_src[2 * EMAX];        // CSR src indices (A at [0,Ea), B at [Ea,..))
__device__ int g_bsums[512];
// Prepped weight chunks: 18 chunks of [128 n x 64 k] bf16, XOR-swizzled, hi/lo.
__device__ __nv_bfloat16 g_Bhi[18 * 8192];
__device__ __nv_bfloat16 g_Blo[18 * 8192];

// ---------------------------------------------------------------------------
// Helpers
// ---------------------------------------------------------------------------
__device__ __forceinline__ float leaky(float v) {
    return v >= 0.0f ? v : NEG_SLOPE * v;
}
__device__ __forceinline__ float relu_(float v) { return fmaxf(v, 0.0f); }

__device__ __forceinline__ uint32_t smem_u32(const void* p) {
    uint32_t a;
    asm("{ .reg .u64 t; cvta.to.shared.u64 t, %1; cvt.u32.u64 %0, t; }"
        : "=r"(a) : "l"(p));
    return a;
}

__device__ __forceinline__ void ldsm4(uint32_t* r, uint32_t addr) {
    asm volatile("ldmatrix.sync.aligned.m8n8.x4.shared.b16 {%0,%1,%2,%3}, [%4];"
                 : "=r"(r[0]), "=r"(r[1]), "=r"(r[2]), "=r"(r[3]) : "r"(addr));
}

__device__ __forceinline__ void mma16816(float* c, const uint32_t* a,
                                         uint32_t b0, uint32_t b1) {
    asm volatile(
        "mma.sync.aligned.m16n8k16.row.col.f32.bf16.bf16.f32 "
        "{%0,%1,%2,%3}, {%4,%5,%6,%7}, {%8,%9}, {%0,%1,%2,%3};"
        : "+f"(c[0]), "+f"(c[1]), "+f"(c[2]), "+f"(c[3])
        : "r"(a[0]), "r"(a[1]), "r"(a[2]), "r"(a[3]), "r"(b0), "r"(b1));
}

// ---------------------------------------------------------------------------
// CSR build kernels
// ---------------------------------------------------------------------------
__global__ void zero_kernel(int* p, int n) {
    int i = blockIdx.x * blockDim.x + threadIdx.x;
    if (i < n) p[i] = 0;
}

// one pass over an edge set: row histogram (degree) + col histogram (CSR)
__global__ void hist2_kernel(const int* __restrict__ rows,
                             const int* __restrict__ cols,
                             int* __restrict__ rowcnt,
                             int* __restrict__ colcnt, int E) {
    int e = blockIdx.x * blockDim.x + threadIdx.x;
    if (e >= E) return;
    atomicAdd(&rowcnt[rows[e]], 1);
    atomicAdd(&colcnt[cols[e]], 1);
}

__global__ void deg_fin_kernel(const int* __restrict__ cnt,
                               float* __restrict__ dis,
                               float* __restrict__ inv, int n) {
    int i = blockIdx.x * blockDim.x + threadIdx.x;
    if (i < n) {
        float d = (float)(cnt[i] + 1);
        dis[i] = rsqrtf(d);
        inv[i] = 1.0f / d;
    }
}

// two-level exclusive scan: 1024 elems per block (256 thr x 4)
__global__ void scan_block_kernel(const int* __restrict__ in, int* __restrict__ out,
                                  int* __restrict__ bsums, int n) {
    __shared__ int sh[256];
    const int base = blockIdx.x * 1024;
    const int t = threadIdx.x;
    int v[4]; int s = 0;
#pragma unroll
    for (int j = 0; j < 4; j++) {
        int i = base + t * 4 + j;
        v[j] = (i < n) ? in[i] : 0;
        s += v[j];
    }
    sh[t] = s;
    __syncthreads();
    for (int off = 1; off < 256; off <<= 1) {
        int x = (t >= off) ? sh[t - off] : 0;
        __syncthreads();
        sh[t] += x;
        __syncthreads();
    }
    int run = (t > 0) ? sh[t - 1] : 0;
    if (t == 255) bsums[blockIdx.x] = sh[255];
#pragma unroll
    for (int j = 0; j < 4; j++) {
        int i = base + t * 4 + j;
        if (i < n) out[i] = run;
        run += v[j];
    }
}

__global__ void scan_sums_kernel(int* bsums, int nb) {
    __shared__ int sh[512];
    int t = threadIdx.x;
    sh[t] = (t < nb) ? bsums[t] : 0;
    __syncthreads();
    for (int off = 1; off < 512; off <<= 1) {
        int x = (t >= off) ? sh[t - off] : 0;
        __syncthreads();
        sh[t] += x;
        __syncthreads();
    }
    if (t < nb) bsums[t] = (t > 0) ? sh[t - 1] : 0;
}

__global__ void scan_add_kernel(int* __restrict__ out, const int* __restrict__ bsums,
                                int n) {
    int i = blockIdx.x * blockDim.x + threadIdx.x;
    if (i < n) out[i] += bsums[i >> 10];
}

// CSR fill: src list bucketed by destination (col)
__global__ void fill_kernel(const int* __restrict__ rows, const int* __restrict__ cols,
                            const int* __restrict__ offs, int* __restrict__ cursor,
                            int* __restrict__ src, int E, int obase) {
    int e = blockIdx.x * blockDim.x + threadIdx.x;
    if (e >= E) return;
    int c = cols[e];
    int pos = offs[obase + c] + atomicAdd(&cursor[obase + c], 1);
    src[pos] = rows[e];
}

// ---------------------------------------------------------------------------
// Merged weight prep: 18 chunks of [128n x 64k], swizzled bf16 hi/lo
// ---------------------------------------------------------------------------
__global__ void prep_all_kernel(const float* __restrict__ enc_w1,
                                const float* __restrict__ enc_w2,
                                const float* __restrict__ conv_w,
                                const float* __restrict__ reconv_w,
                                __nv_bfloat16* __restrict__ BH,
                                __nv_bfloat16* __restrict__ BL) {
    const int chunk = blockIdx.x >> 5;
    const int idx = (blockIdx.x & 31) * 256 + threadIdx.x;  // 0..8191
    const int n = idx >> 6;
    const int k = idx & 63;
    const float* W; int ldn, k0, n0, kcount;
    if (chunk < 2)      { W = enc_w1; ldn = 256; k0 = 0; n0 = chunk * 128; kcount = 32; }
    else if (chunk < 6) { W = enc_w2; ldn = 128; k0 = (chunk - 2) * 64; n0 = 0; kcount = 64; }
    else if (chunk < 12) {
        int l = (chunk - 6) >> 1, c = (chunk - 6) & 1;
        W = conv_w + (size_t)l * 16384; ldn = 128; k0 = c * 64; n0 = 0; kcount = 64;
    } else {
        int l = (chunk - 12) >> 1, c = (chunk - 12) & 1;
        W = reconv_w + (size_t)l * 16384; ldn = 128; k0 = c * 64; n0 = 0; kcount = 64;
    }
    float v = (k < kcount) ? W[(size_t)(k0 + k) * ldn + n0 + n] : 0.0f;
    __nv_bfloat16 h = __float2bfloat16(v);
    __nv_bfloat16 l = __float2bfloat16(v - __bfloat162float(h));
    int off = n * 128 + ((k * 2) ^ ((n & 7) << 4));
    BH[(size_t)chunk * 8192 + (off >> 1)] = h;
    BL[(size_t)chunk * 8192 + (off >> 1)] = l;
}

// ---------------------------------------------------------------------------
// Tensor-core GEMM (mma.sync bf16 3-split): out[M,128] = A[M,KV] @ W + bias
//   act=1: leaky applied. Writes only `out` (stride ostride, col offset colofs).
// ---------------------------------------------------------------------------
#define SM_A_HI 0
#define SM_A_LO 16384
#define SM_B_HI 32768
#define SM_B_LO 49152
#define SMEM_TC 65536

__global__ void __launch_bounds__(256, 2)
gemm_tc_kernel(const float* __restrict__ A, int lda, int M,
               const __nv_bfloat16* __restrict__ BhiG,
               const __nv_bfloat16* __restrict__ BloG,
               int kchunks, int KV,
               const float* __restrict__ bias,
               float* __restrict__ out, int ostride, int colofs, int act) {
    extern __shared__ char sm[];
    const uint32_t sb = smem_u32(sm);
    const int tid = threadIdx.x;
    const int w = tid >> 5;
    const int lane = tid & 31;
    const int wm = w & 3;
    const int wn = w >> 2;
    const int row0 = blockIdx.x * 128;

    float acc[2][8][4];
#pragma unroll
    for (int a = 0; a < 2; a++)
#pragma unroll
        for (int b = 0; b < 8; b++)
#pragma unroll
            for (int c = 0; c < 4; c++) acc[a][b][c] = 0.0f;

    for (int ck = 0; ck < kchunks; ck++) {
        const int kbase = ck * 64;
        int kcols = KV - kbase; if (kcols > 64) kcols = 64;
        const int ksteps = (kcols + 15) >> 4;

        {
            const float4* sh = (const float4*)(BhiG + (size_t)ck * 8192);
            const float4* sl = (const float4*)(BloG + (size_t)ck * 8192);
            float4* dh = (float4*)(sm + SM_B_HI);
            float4* dl = (float4*)(sm + SM_B_LO);
            for (int i = tid; i < 1024; i += 256) { dh[i] = sh[i]; dl[i] = sl[i]; }
        }

#pragma unroll
        for (int i = 0; i < 8; i++) {
            const int idx = tid + i * 256;
            const int r = idx >> 4;
            const int c4 = idx & 15;
            float4 v = make_float4(0.f, 0.f, 0.f, 0.f);
            const int gr = row0 + r;
            if (gr < M && c4 * 4 < kcols)
                v = *(const float4*)(A + (size_t)gr * lda + kbase + c4 * 4);
            __nv_bfloat16 hx = __float2bfloat16(v.x);
            __nv_bfloat16 hy = __float2bfloat16(v.y);
            __nv_bfloat16 hz = __float2bfloat16(v.z);
            __nv_bfloat16 hw = __float2bfloat16(v.w);
            __nv_bfloat16 lx = __float2bfloat16(v.x - __bfloat162float(hx));
            __nv_bfloat16 ly = __float2bfloat16(v.y - __bfloat162float(hy));
            __nv_bfloat16 lz = __float2bfloat16(v.z - __bfloat162float(hz));
            __nv_bfloat16 lw = __float2bfloat16(v.w - __bfloat162float(hw));
            uint32_t hi01 = ((uint32_t)__bfloat16_as_ushort(hy) << 16) |
                             (uint32_t)__bfloat16_as_ushort(hx);
            uint32_t hi23 = ((uint32_t)__bfloat16_as_ushort(hw) << 16) |
                             (uint32_t)__bfloat16_as_ushort(hz);
            uint32_t lo01 = ((uint32_t)__bfloat16_as_ushort(ly) << 16) |
                             (uint32_t)__bfloat16_as_ushort(lx);
            uint32_t lo23 = ((uint32_t)__bfloat16_as_ushort(lw) << 16) |
                             (uint32_t)__bfloat16_as_ushort(lz);
            int off = r * 128 + ((c4 * 8) ^ ((r & 7) << 4));
            *(uint2*)(sm + SM_A_HI + off) = make_uint2(hi01, hi23);
            *(uint2*)(sm + SM_A_LO + off) = make_uint2(lo01, lo23);
        }
        __syncthreads();

        for (int ks = 0; ks < ksteps; ks++) {
            uint32_t ah[2][4], al[2][4];
            {
                const int rr = (lane & 15);
                const int colb = ks * 32 + (lane & 16);
#pragma unroll
                for (int mt = 0; mt < 2; mt++) {
                    const int row = wm * 32 + mt * 16 + rr;
                    const uint32_t ad = (uint32_t)(row * 128 + (colb ^ ((row & 7) << 4)));
                    ldsm4(ah[mt], sb + SM_A_HI + ad);
                    ldsm4(al[mt], sb + SM_A_LO + ad);
                }
            }
#pragma unroll
            for (int np = 0; np < 4; np++) {
                const int nb = wn * 64 + np * 16;
                const int n = nb + (lane & 7) + ((lane & 16) >> 1);
                const int colb = ks * 32 + ((lane & 8) << 1);
                const uint32_t bd = (uint32_t)(n * 128 + (colb ^ ((n & 7) << 4)));
                uint32_t bh[4], bl[4];
                ldsm4(bh, sb + SM_B_HI + bd);
                ldsm4(bl, sb + SM_B_LO + bd);
#pragma unroll
                for (int mt = 0; mt < 2; mt++) {
#pragma unroll
                    for (int nt = 0; nt < 2; nt++) {
                        float* c = acc[mt][np * 2 + nt];
                        mma16816(c, ah[mt], bh[nt * 2], bh[nt * 2 + 1]);
                        mma16816(c, ah[mt], bl[nt * 2], bl[nt * 2 + 1]);
                        mma16816(c, al[mt], bh[nt * 2], bh[nt * 2 + 1]);
                    }
                }
            }
        }
        __syncthreads();
    }

    const int quad = lane >> 2;
    const int tq = lane & 3;
#pragma unroll
    for (int mt = 0; mt < 2; mt++) {
#pragma unroll
        for (int half = 0; half < 2; half++) {
            const int gr = row0 + wm * 32 + mt * 16 + half * 8 + quad;
            if (gr >= M) continue;
            float* po = out + (size_t)gr * ostride + colofs + wn * 64;
#pragma unroll
            for (int j = 0; j < 8; j++) {
                const int col = j * 8 + tq * 2;
                float c0 = acc[mt][j][half * 2 + 0] + __ldg(bias + wn * 64 + col);
                float c1 = acc[mt][j][half * 2 + 1] + __ldg(bias + wn * 64 + col + 1);
                float2 o;
                o.x = act ? leaky(c0) : c0;
                o.y = act ? leaky(c1) : c1;
                *(float2*)(po + col) = o;
            }
        }
    }
}

// ---------------------------------------------------------------------------
// CSR gather-aggregate (pass A): warp per destination node.
// agg[c] = relu(xl[c]+root)*inv[c] + dis[c] * sum_e dis[src_e]*relu(xl[src_e])
// ---------------------------------------------------------------------------
__global__ void agg_kernel(const float* __restrict__ xl,
                           const int* __restrict__ offs,
                           const int* __restrict__ cnt,
                           const int* __restrict__ src,
                           const float* __restrict__ dis,
                           const float* __restrict__ inv,
                           const float* __restrict__ root,
                           float* __restrict__ agg, int Nn, int obase) {
    const int c = blockIdx.x * 8 + (threadIdx.x >> 5);
    if (c >= Nn) return;
    const int lane = threadIdx.x & 31;

    float4 xv = ((const float4*)xl)[(size_t)c * 32 + lane];
    float4 rv = ((const float4*)root)[lane];
    const float iv = __ldg(inv + c);
    float4 acc;
    acc.x = relu_(xv.x + rv.x) * iv;
    acc.y = relu_(xv.y + rv.y) * iv;
    acc.z = relu_(xv.z + rv.z) * iv;
    acc.w = relu_(xv.w + rv.w) * iv;

    const int o = __ldg(offs + obase + c);
    const int k = __ldg(cnt + obase + c);
    const float dc = __ldg(dis + c);
    float4 na = make_float4(0.f, 0.f, 0.f, 0.f);
    for (int j = 0; j < k; j++) {
        const int s = __ldg(src + o + j);
        const float ds = __ldg(dis + s);
        float4 v = ((const float4*)xl)[(size_t)s * 32 + lane];
        na.x += ds * relu_(v.x);
        na.y += ds * relu_(v.y);
        na.z += ds * relu_(v.z);
        na.w += ds * relu_(v.w);
    }
    acc.x += dc * na.x; acc.y += dc * na.y;
    acc.z += dc * na.z; acc.w += dc * na.w;
    ((float4*)agg)[(size_t)c * 32 + lane] = acc;
}

// ---------------------------------------------------------------------------
// CSR gather-aggregate (pass B) fused with LayerNorm + LeakyReLU + residual.
// hnext[c] = leaky(LN(gcn_out[c])*g + b) + hprev[c]
// ---------------------------------------------------------------------------
__global__ void agg_ln_kernel(const float* __restrict__ xl,
                              const int* __restrict__ offs,
                              const int* __restrict__ cnt,
                              const int* __restrict__ src,
                              const float* __restrict__ dis,
                              const float* __restrict__ inv,
                              const float* __restrict__ root,
                              const float* __restrict__ g,
                              const float* __restrict__ b,
                              const float* __restrict__ hprev,
                              float* __restrict__ hnext, int Nn, int obase) {
    const int c = blockIdx.x * 8 + (threadIdx.x >> 5);
    if (c >= Nn) return;
    const int lane = threadIdx.x & 31;

    float4 xv = ((const float4*)xl)[(size_t)c * 32 + lane];
    float4 rv = ((const float4*)root)[lane];
    const float iv = __ldg(inv + c);
    float4 acc;
    acc.x = relu_(xv.x + rv.x) * iv;
    acc.y = relu_(xv.y + rv.y) * iv;
    acc.z = relu_(xv.z + rv.z) * iv;
    acc.w = relu_(xv.w + rv.w) * iv;

    const int o = __ldg(offs + obase + c);
    const int k = __ldg(cnt + obase + c);
    const float dc = __ldg(dis + c);
    float4 na = make_float4(0.f, 0.f, 0.f, 0.f);
    for (int j = 0; j < k; j++) {
        const int s = __ldg(src + o + j);
        const float ds = __ldg(dis + s);
        float4 v = ((const float4*)xl)[(size_t)s * 32 + lane];
        na.x += ds * relu_(v.x);
        na.y += ds * relu_(v.y);
        na.z += ds * relu_(v.z);
        na.w += ds * relu_(v.w);
    }
    acc.x += dc * na.x; acc.y += dc * na.y;
    acc.z += dc * na.z; acc.w += dc * na.w;

    // LayerNorm over the 128-wide row
    float s1 = acc.x + acc.y + acc.z + acc.w;
#pragma unroll
    for (int off = 16; off > 0; off >>= 1) s1 += __shfl_xor_sync(0xffffffffu, s1, off);
    const float mu = s1 * (1.0f / 128.0f);
    float dx = acc.x - mu, dy = acc.y - mu, dz = acc.z - mu, dw = acc.w - mu;
    float q = dx * dx + dy * dy + dz * dz + dw * dw;
#pragma unroll
    for (int off = 16; off > 0; off >>= 1) q += __shfl_xor_sync(0xffffffffu, q, off);
    const float rstd = rsqrtf(q * (1.0f / 128.0f) + LN_EPS);

    float4 gg = ((const float4*)g)[lane];
    float4 bb = ((const float4*)b)[lane];
    float4 hp = ((const float4*)hprev)[(size_t)c * 32 + lane];
    float4 out;
    out.x = leaky(dx * rstd * gg.x + bb.x) + hp.x;
    out.y = leaky(dy * rstd * gg.y + bb.y) + hp.y;
    out.z = leaky(dz * rstd * gg.z + bb.z) + hp.z;
    out.w = leaky(dw * rstd * gg.w + bb.w) + hp.w;
    ((float4*)hnext)[(size_t)c * 32 + lane] = out;
}

// ---------------------------------------------------------------------------
// JK-concat output
// ---------------------------------------------------------------------------
__global__ void concat_kernel(const float* __restrict__ h0,
                              const float* __restrict__ h1,
                              const float* __restrict__ h2,
                              const float* __restrict__ h3,
                              float* __restrict__ out, int rows) {
    int idx = blockIdx.x * blockDim.x + threadIdx.x;
    if (idx >= rows * 128) return;
    int row = idx >> 7;
    int c = idx & 127;
    int l = c >> 5;
    int j = c & 31;
    const float* h = (l == 0) ? h0 : (l == 1) ? h1 : (l == 2) ? h2 : h3;
    ((float4*)out)[idx] = ((const float4*)h)[(size_t)row * 32 + j];
}

// ---------------------------------------------------------------------------
// Launch
// ---------------------------------------------------------------------------
extern "C" void kernel_launch(void* const* d_in, const int* in_sizes, int n_in,
                              void* d_out, int out_size) {
    const float* x        = (const float*)d_in[0];
    const float* enc_w1   = (const float*)d_in[1];
    const float* enc_b1   = (const float*)d_in[2];
    const float* enc_w2   = (const float*)d_in[3];
    const float* enc_b2   = (const float*)d_in[4];
    const float* conv_w   = (const float*)d_in[5];
    const float* conv_b   = (const float*)d_in[6];
    const float* conv_rt  = (const float*)d_in[7];
    const float* reconv_w = (const float*)d_in[8];
    const float* reconv_b = (const float*)d_in[9];
    const float* reconv_rt= (const float*)d_in[10];
    const float* ln_g     = (const float*)d_in[11];
    const float* ln_b     = (const float*)d_in[12];
    const int*   eA       = (const int*)d_in[13];
    const int*   eB       = (const int*)d_in[14];

    const int N  = in_sizes[0] / 32;
    const int Ea = in_sizes[13] / 2;
    const int Eb = in_sizes[14] / 2;
    const int rows_out = out_size / 512;

    const int* rowsA = eA; const int* colsA = eA + Ea;
    const int* rowsB = eB; const int* colsB = eB + Eb;

    void* p;
    cudaGetSymbolAddress(&p, g_H);    float* H    = (float*)p;
    cudaGetSymbolAddress(&p, g_XL);   float* XL   = (float*)p;
    cudaGetSymbolAddress(&p, g_AGG);  float* AGG  = (float*)p;
    cudaGetSymbolAddress(&p, g_H1);   float* H1E  = (float*)p;
    cudaGetSymbolAddress(&p, g_disA); float* disA = (float*)p;
    cudaGetSymbolAddress(&p, g_disB); float* disB = (float*)p;
    cudaGetSymbolAddress(&p, g_invA); float* invA = (float*)p;
    cudaGetSymbolAddress(&p, g_invB); float* invB = (float*)p;
    cudaGetSymbolAddress(&p, g_icsr); int* icsr   = (int*)p;
    cudaGetSymbolAddress(&p, g_offs); int* offs   = (int*)p;
    cudaGetSymbolAddress(&p, g_src);  int* src    = (int*)p;
    cudaGetSymbolAddress(&p, g_bsums);int* bsums  = (int*)p;
    cudaGetSymbolAddress(&p, g_Bhi);  __nv_bfloat16* BH = (__nv_bfloat16*)p;
    cudaGetSymbolAddress(&p, g_Blo);  __nv_bfloat16* BL = (__nv_bfloat16*)p;

    int* rowcntA = icsr;
    int* rowcntB = icsr + NMAX;
    int* colcnt  = icsr + 2 * NMAX;   // 2N (A then B)
    int* cursor  = icsr + 4 * NMAX;   // 2N

    const size_t hstride = (size_t)NMAX * EMB;

    cudaFuncSetAttribute(gemm_tc_kernel,
                         cudaFuncAttributeMaxDynamicSharedMemorySize, SMEM_TC);

    // ---- weight prep (single merged launch) ----
    prep_all_kernel<<<18 * 32, 256>>>(enc_w1, enc_w2, conv_w, reconv_w, BH, BL);

    // ---- CSR build + degrees ----
    zero_kernel<<<(6 * NMAX + 255) / 256, 256>>>(icsr, 6 * NMAX);
    hist2_kernel<<<(Ea + 255) / 256, 256>>>(rowsA, colsA, rowcntA, colcnt, Ea);
    hist2_kernel<<<(Eb + 255) / 256, 256>>>(rowsB, colsB, rowcntB, colcnt + NMAX, Eb);
    deg_fin_kernel<<<(N + 255) / 256, 256>>>(rowcntA, disA, invA, N);
    deg_fin_kernel<<<(N + 255) / 256, 256>>>(rowcntB, disB, invB, N);
    {
        const int n2 = 2 * NMAX;
        const int nb = (n2 + 1023) / 1024;   // 391
        scan_block_kernel<<<nb, 256>>>(colcnt, offs, bsums, n2);
        scan_sums_kernel<<<1, 512>>>(bsums, nb);
        scan_add_kernel<<<(n2 + 255) / 256, 256>>>(offs, bsums, n2);
    }
    fill_kernel<<<(Ea + 255) / 256, 256>>>(rowsA, colsA, offs, cursor, src, Ea, 0);
    fill_kernel<<<(Eb + 255) / 256, 256>>>(rowsB, colsB, offs, cursor, src, Eb, NMAX);

    const int tiles = (N + 127) / 128;
    const int wblocks = (N + 7) / 8;

    // ---- encoder ----
    gemm_tc_kernel<<<tiles, 256, SMEM_TC>>>(x, 32, N,
        BH + 0 * 8192, BL + 0 * 8192, 1, 32, enc_b1, H1E, 256, 0, 1);
    gemm_tc_kernel<<<tiles, 256, SMEM_TC>>>(x, 32, N,
        BH + 1 * 8192, BL + 1 * 8192, 1, 32, enc_b1 + 128, H1E, 256, 128, 1);
    gemm_tc_kernel<<<tiles, 256, SMEM_TC>>>(H1E, 256, N,
        BH + 2 * 8192, BL + 2 * 8192, 4, 256, enc_b2, H, 128, 0, 1);

    // ---- GCN layers ----
    for (int l = 0; l < 3; l++) {
        const float* hl = H + (size_t)l * hstride;
        float* hn = H + (size_t)(l + 1) * hstride;

        // conv (edge set A): linear -> XL, then CSR aggregate -> AGG
        gemm_tc_kernel<<<tiles, 256, SMEM_TC>>>(hl, 128, N,
            BH + (6 + 2 * l) * 8192, BL + (6 + 2 * l) * 8192, 2, 128,
            conv_b + l * EMB, XL, 128, 0, 0);
        agg_kernel<<<wblocks, 256>>>(XL, offs, colcnt, src, disA, invA,
                                     conv_rt + l * EMB, AGG, N, 0);

        // reconv (edge set B): linear -> XL, then aggregate + LN + residual -> hn
        gemm_tc_kernel<<<tiles, 256, SMEM_TC>>>(AGG, 128, N,
            BH + (12 + 2 * l) * 8192, BL + (12 + 2 * l) * 8192, 2, 128,
            reconv_b + l * EMB, XL, 128, 0, 0);
        agg_ln_kernel<<<wblocks, 256>>>(XL, offs, colcnt, src, disB, invB,
                                        reconv_rt + l * EMB,
                                        ln_g + l * EMB, ln_b + l * EMB,
                                        hl, hn, N, NMAX);
    }

    // ---- concat output ----
    concat_kernel<<<(rows_out * 128 + 255) / 256, 256>>>(
        H, H + hstride, H + 2 * hstride, H + 3 * hstride, (float*)d_out, rows_out);
}

// round 10
// speedup vs baseline: 1.9183x; 1.1389x over previous
#include <cuda_runtime.h>
#include <cuda_bf16.h>
#include <cuda_fp16.h>
#include <cstddef>
#include <cstdint>

// ---------------------------------------------------------------------------
// Problem constants
// ---------------------------------------------------------------------------
#define NMAX   200000
#define EMAX   650000
#define EMB    128
#define ENC1   256
#define NEG_SLOPE 0.1f
#define LN_EPS 1e-5f

// ---------------------------------------------------------------------------
// Scratch (static __device__ arrays; no allocations allowed)
// ---------------------------------------------------------------------------
__device__ float g_H[4][(size_t)NMAX * EMB];   // h_list[0..3]
__device__ float g_XL[(size_t)NMAX * EMB];     // pass-B init buffer
__device__ float g_AGG[(size_t)NMAX * EMB];    // pass-A init/result buffer
__device__ float g_H1[(size_t)NMAX * ENC1];    // encoder intermediate
__device__ __half2 g_Y[(size_t)NMAX * 64];     // fp16 messages (128 halfs/row)
__device__ float g_disA[NMAX];
__device__ float g_disB[NMAX];
__device__ float g_invA[NMAX];
__device__ float g_invB[NMAX];
// CSR scratch: [0,N) rowcntA | [N,2N) rowcntB | [2N,4N) colcnt (A then B)
//              [4N,6N) cursors (A then B)
__device__ int g_icsr[6 * NMAX];
__device__ int g_offs[2 * NMAX];
__device__ int g_src[2 * EMAX];
__device__ int g_bsums[512];
// Prepped weight chunks: 18 chunks of [128 n x 64 k] bf16, XOR-swizzled, hi/lo.
__device__ __nv_bfloat16 g_Bhi[18 * 8192];
__device__ __nv_bfloat16 g_Blo[18 * 8192];

// ---------------------------------------------------------------------------
// Helpers
// ---------------------------------------------------------------------------
__device__ __forceinline__ float leaky(float v) {
    return v >= 0.0f ? v : NEG_SLOPE * v;
}
__device__ __forceinline__ float relu_(float v) { return fmaxf(v, 0.0f); }

__device__ __forceinline__ uint32_t smem_u32(const void* p) {
    uint32_t a;
    asm("{ .reg .u64 t; cvta.to.shared.u64 t, %1; cvt.u32.u64 %0, t; }"
        : "=r"(a) : "l"(p));
    return a;
}

__device__ __forceinline__ void ldsm4(uint32_t* r, uint32_t addr) {
    asm volatile("ldmatrix.sync.aligned.m8n8.x4.shared.b16 {%0,%1,%2,%3}, [%4];"
                 : "=r"(r[0]), "=r"(r[1]), "=r"(r[2]), "=r"(r[3]) : "r"(addr));
}

__device__ __forceinline__ void mma16816(float* c, const uint32_t* a,
                                         uint32_t b0, uint32_t b1) {
    asm volatile(
        "mma.sync.aligned.m16n8k16.row.col.f32.bf16.bf16.f32 "
        "{%0,%1,%2,%3}, {%4,%5,%6,%7}, {%8,%9}, {%0,%1,%2,%3};"
        : "+f"(c[0]), "+f"(c[1]), "+f"(c[2]), "+f"(c[3])
        : "r"(a[0]), "r"(a[1]), "r"(a[2]), "r"(a[3]), "r"(b0), "r"(b1));
}

// ---------------------------------------------------------------------------
// CSR build kernels
// ---------------------------------------------------------------------------
__global__ void zero_kernel(int* p, int n) {
    int i = blockIdx.x * blockDim.x + threadIdx.x;
    if (i < n) p[i] = 0;
}

__global__ void hist2_kernel(const int* __restrict__ rows,
                             const int* __restrict__ cols,
                             int* __restrict__ rowcnt,
                             int* __restrict__ colcnt, int E) {
    int e = blockIdx.x * blockDim.x + threadIdx.x;
    if (e >= E) return;
    atomicAdd(&rowcnt[rows[e]], 1);
    atomicAdd(&colcnt[cols[e]], 1);
}

__global__ void deg_fin_kernel(const int* __restrict__ cnt,
                               float* __restrict__ dis,
                               float* __restrict__ inv, int n) {
    int i = blockIdx.x * blockDim.x + threadIdx.x;
    if (i < n) {
        float d = (float)(cnt[i] + 1);
        dis[i] = rsqrtf(d);
        inv[i] = 1.0f / d;
    }
}

__global__ void scan_block_kernel(const int* __restrict__ in, int* __restrict__ out,
                                  int* __restrict__ bsums, int n) {
    __shared__ int sh[256];
    const int base = blockIdx.x * 1024;
    const int t = threadIdx.x;
    int v[4]; int s = 0;
#pragma unroll
    for (int j = 0; j < 4; j++) {
        int i = base + t * 4 + j;
        v[j] = (i < n) ? in[i] : 0;
        s += v[j];
    }
    sh[t] = s;
    __syncthreads();
    for (int off = 1; off < 256; off <<= 1) {
        int x = (t >= off) ? sh[t - off] : 0;
        __syncthreads();
        sh[t] += x;
        __syncthreads();
    }
    int run = (t > 0) ? sh[t - 1] : 0;
    if (t == 255) bsums[blockIdx.x] = sh[255];
#pragma unroll
    for (int j = 0; j < 4; j++) {
        int i = base + t * 4 + j;
        if (i < n) out[i] = run;
        run += v[j];
    }
}

__global__ void scan_sums_kernel(int* bsums, int nb) {
    __shared__ int sh[512];
    int t = threadIdx.x;
    sh[t] = (t < nb) ? bsums[t] : 0;
    __syncthreads();
    for (int off = 1; off < 512; off <<= 1) {
        int x = (t >= off) ? sh[t - off] : 0;
        __syncthreads();
        sh[t] += x;
        __syncthreads();
    }
    if (t < nb) bsums[t] = (t > 0) ? sh[t - 1] : 0;
}

__global__ void scan_add_kernel(int* __restrict__ out, const int* __restrict__ bsums,
                                int n) {
    int i = blockIdx.x * blockDim.x + threadIdx.x;
    if (i < n) out[i] += bsums[i >> 10];
}

__global__ void fill_kernel(const int* __restrict__ rows, const int* __restrict__ cols,
                            const int* __restrict__ offs, int* __restrict__ cursor,
                            int* __restrict__ src, int E, int obase) {
    int e = blockIdx.x * blockDim.x + threadIdx.x;
    if (e >= E) return;
    int c = cols[e];
    int pos = offs[obase + c] + atomicAdd(&cursor[obase + c], 1);
    src[pos] = rows[e];
}

// ---------------------------------------------------------------------------
// Merged weight prep: 18 chunks of [128n x 64k], swizzled bf16 hi/lo
// ---------------------------------------------------------------------------
__global__ void prep_all_kernel(const float* __restrict__ enc_w1,
                                const float* __restrict__ enc_w2,
                                const float* __restrict__ conv_w,
                                const float* __restrict__ reconv_w,
                                __nv_bfloat16* __restrict__ BH,
                                __nv_bfloat16* __restrict__ BL) {
    const int chunk = blockIdx.x >> 5;
    const int idx = (blockIdx.x & 31) * 256 + threadIdx.x;
    const int n = idx >> 6;
    const int k = idx & 63;
    const float* W; int ldn, k0, n0, kcount;
    if (chunk < 2)      { W = enc_w1; ldn = 256; k0 = 0; n0 = chunk * 128; kcount = 32; }
    else if (chunk < 6) { W = enc_w2; ldn = 128; k0 = (chunk - 2) * 64; n0 = 0; kcount = 64; }
    else if (chunk < 12) {
        int l = (chunk - 6) >> 1, c = (chunk - 6) & 1;
        W = conv_w + (size_t)l * 16384; ldn = 128; k0 = c * 64; n0 = 0; kcount = 64;
    } else {
        int l = (chunk - 12) >> 1, c = (chunk - 12) & 1;
        W = reconv_w + (size_t)l * 16384; ldn = 128; k0 = c * 64; n0 = 0; kcount = 64;
    }
    float v = (k < kcount) ? W[(size_t)(k0 + k) * ldn + n0 + n] : 0.0f;
    __nv_bfloat16 h = __float2bfloat16(v);
    __nv_bfloat16 l = __float2bfloat16(v - __bfloat162float(h));
    int off = n * 128 + ((k * 2) ^ ((n & 7) << 4));
    BH[(size_t)chunk * 8192 + (off >> 1)] = h;
    BL[(size_t)chunk * 8192 + (off >> 1)] = l;
}

// ---------------------------------------------------------------------------
// Tensor-core GEMM (mma.sync bf16 3-split): d = A[M,KV] @ W + bias
//  mode 0: out[gr*ostride+colofs+n] = act? leaky(d) : d
//          if (aux && gr<rows_aux) also aux[gr*512+aofs+n] = same value
//  mode 1 (GCN prep): out[gr*128+n] = relu(d+root[n]) * inv[gr]   (init)
//                     ybuf[gr][n]   = half( dis[gr] * relu(d) )   (message)
// ---------------------------------------------------------------------------
#define SM_A_HI 0
#define SM_A_LO 16384
#define SM_B_HI 32768
#define SM_B_LO 49152
#define SMEM_TC 65536

__global__ void __launch_bounds__(256, 2)
gemm_tc_kernel(const float* __restrict__ A, int lda, int M,
               const __nv_bfloat16* __restrict__ BhiG,
               const __nv_bfloat16* __restrict__ BloG,
               int kchunks, int KV,
               const float* __restrict__ bias,
               float* __restrict__ out, int ostride, int colofs, int act,
               float* __restrict__ aux, int aofs, int rows_aux,
               int mode,
               const float* __restrict__ root,
               const float* __restrict__ dis,
               const float* __restrict__ inv,
               __half2* __restrict__ ybuf) {
    extern __shared__ char sm[];
    const uint32_t sb = smem_u32(sm);
    const int tid = threadIdx.x;
    const int w = tid >> 5;
    const int lane = tid & 31;
    const int wm = w & 3;
    const int wn = w >> 2;
    const int row0 = blockIdx.x * 128;

    float acc[2][8][4];
#pragma unroll
    for (int a = 0; a < 2; a++)
#pragma unroll
        for (int b = 0; b < 8; b++)
#pragma unroll
            for (int c = 0; c < 4; c++) acc[a][b][c] = 0.0f;

    for (int ck = 0; ck < kchunks; ck++) {
        const int kbase = ck * 64;
        int kcols = KV - kbase; if (kcols > 64) kcols = 64;
        const int ksteps = (kcols + 15) >> 4;

        {
            const float4* sh = (const float4*)(BhiG + (size_t)ck * 8192);
            const float4* sl = (const float4*)(BloG + (size_t)ck * 8192);
            float4* dh = (float4*)(sm + SM_B_HI);
            float4* dl = (float4*)(sm + SM_B_LO);
            for (int i = tid; i < 1024; i += 256) { dh[i] = sh[i]; dl[i] = sl[i]; }
        }

#pragma unroll
        for (int i = 0; i < 8; i++) {
            const int idx = tid + i * 256;
            const int r = idx >> 4;
            const int c4 = idx & 15;
            float4 v = make_float4(0.f, 0.f, 0.f, 0.f);
            const int gr = row0 + r;
            if (gr < M && c4 * 4 < kcols)
                v = *(const float4*)(A + (size_t)gr * lda + kbase + c4 * 4);
            __nv_bfloat16 hx = __float2bfloat16(v.x);
            __nv_bfloat16 hy = __float2bfloat16(v.y);
            __nv_bfloat16 hz = __float2bfloat16(v.z);
            __nv_bfloat16 hw = __float2bfloat16(v.w);
            __nv_bfloat16 lx = __float2bfloat16(v.x - __bfloat162float(hx));
            __nv_bfloat16 ly = __float2bfloat16(v.y - __bfloat162float(hy));
            __nv_bfloat16 lz = __float2bfloat16(v.z - __bfloat162float(hz));
            __nv_bfloat16 lw = __float2bfloat16(v.w - __bfloat162float(hw));
            uint32_t hi01 = ((uint32_t)__bfloat16_as_ushort(hy) << 16) |
                             (uint32_t)__bfloat16_as_ushort(hx);
            uint32_t hi23 = ((uint32_t)__bfloat16_as_ushort(hw) << 16) |
                             (uint32_t)__bfloat16_as_ushort(hz);
            uint32_t lo01 = ((uint32_t)__bfloat16_as_ushort(ly) << 16) |
                             (uint32_t)__bfloat16_as_ushort(lx);
            uint32_t lo23 = ((uint32_t)__bfloat16_as_ushort(lw) << 16) |
                             (uint32_t)__bfloat16_as_ushort(lz);
            int off = r * 128 + ((c4 * 8) ^ ((r & 7) << 4));
            *(uint2*)(sm + SM_A_HI + off) = make_uint2(hi01, hi23);
            *(uint2*)(sm + SM_A_LO + off) = make_uint2(lo01, lo23);
        }
        __syncthreads();

        for (int ks = 0; ks < ksteps; ks++) {
            uint32_t ah[2][4], al[2][4];
            {
                const int rr = (lane & 15);
                const int colb = ks * 32 + (lane & 16);
#pragma unroll
                for (int mt = 0; mt < 2; mt++) {
                    const int row = wm * 32 + mt * 16 + rr;
                    const uint32_t ad = (uint32_t)(row * 128 + (colb ^ ((row & 7) << 4)));
                    ldsm4(ah[mt], sb + SM_A_HI + ad);
                    ldsm4(al[mt], sb + SM_A_LO + ad);
                }
            }
#pragma unroll
            for (int np = 0; np < 4; np++) {
                const int nb = wn * 64 + np * 16;
                const int n = nb + (lane & 7) + ((lane & 16) >> 1);
                const int colb = ks * 32 + ((lane & 8) << 1);
                const uint32_t bd = (uint32_t)(n * 128 + (colb ^ ((n & 7) << 4)));
                uint32_t bh[4], bl[4];
                ldsm4(bh, sb + SM_B_HI + bd);
                ldsm4(bl, sb + SM_B_LO + bd);
#pragma unroll
                for (int mt = 0; mt < 2; mt++) {
#pragma unroll
                    for (int nt = 0; nt < 2; nt++) {
                        float* c = acc[mt][np * 2 + nt];
                        mma16816(c, ah[mt], bh[nt * 2], bh[nt * 2 + 1]);
                        mma16816(c, ah[mt], bl[nt * 2], bl[nt * 2 + 1]);
                        mma16816(c, al[mt], bh[nt * 2], bh[nt * 2 + 1]);
                    }
                }
            }
        }
        __syncthreads();
    }

    const int quad = lane >> 2;
    const int tq = lane & 3;
#pragma unroll
    for (int mt = 0; mt < 2; mt++) {
#pragma unroll
        for (int half = 0; half < 2; half++) {
            const int gr = row0 + wm * 32 + mt * 16 + half * 8 + quad;
            if (gr >= M) continue;
            if (mode == 0) {
                float* po = out + (size_t)gr * ostride + colofs + wn * 64;
                float* pa = (aux && gr < rows_aux)
                          ? aux + (size_t)gr * 512 + aofs + wn * 64 : nullptr;
#pragma unroll
                for (int j = 0; j < 8; j++) {
                    const int col = j * 8 + tq * 2;
                    float c0 = acc[mt][j][half * 2 + 0] + __ldg(bias + wn * 64 + col);
                    float c1 = acc[mt][j][half * 2 + 1] + __ldg(bias + wn * 64 + col + 1);
                    float2 o;
                    o.x = act ? leaky(c0) : c0;
                    o.y = act ? leaky(c1) : c1;
                    *(float2*)(po + col) = o;
                    if (pa) *(float2*)(pa + col) = o;
                }
            } else {
                const float id = __ldg(inv + gr);
                const float dg = __ldg(dis + gr);
                float* po = out + (size_t)gr * 128 + wn * 64;
                __half2* py = ybuf + (size_t)gr * 64 + wn * 32;
#pragma unroll
                for (int j = 0; j < 8; j++) {
                    const int col = j * 8 + tq * 2;
                    float xl0 = acc[mt][j][half * 2 + 0] + __ldg(bias + wn * 64 + col);
                    float xl1 = acc[mt][j][half * 2 + 1] + __ldg(bias + wn * 64 + col + 1);
                    float2 ini;
                    ini.x = relu_(xl0 + __ldg(root + wn * 64 + col)) * id;
                    ini.y = relu_(xl1 + __ldg(root + wn * 64 + col + 1)) * id;
                    *(float2*)(po + col) = ini;
                    py[col >> 1] = __floats2half2_rn(dg * relu_(xl0), dg * relu_(xl1));
                }
            }
        }
    }
}

// ---------------------------------------------------------------------------
// CSR gather-aggregate (pass A): warp per destination node, in-place on agg.
// agg[c] = init[c] + dis[c] * sum_e y[src_e]     (y fp16)
// ---------------------------------------------------------------------------
__device__ __forceinline__ float4 gather_sum(const __half2* __restrict__ y,
                                             const int* __restrict__ src,
                                             int o, int k, int lane) {
    float4 na = make_float4(0.f, 0.f, 0.f, 0.f);
    int j = 0;
    for (; j + 2 <= k; j += 2) {
        const int s0 = __ldg(src + o + j);
        const int s1 = __ldg(src + o + j + 1);
        const uint2 v0 = *(const uint2*)(y + (size_t)s0 * 64 + lane * 2);
        const uint2 v1 = *(const uint2*)(y + (size_t)s1 * 64 + lane * 2);
        float2 a0 = __half22float2(*(const __half2*)&v0.x);
        float2 a1 = __half22float2(*(const __half2*)&v0.y);
        float2 b0 = __half22float2(*(const __half2*)&v1.x);
        float2 b1 = __half22float2(*(const __half2*)&v1.y);
        na.x += a0.x + b0.x;
        na.y += a0.y + b0.y;
        na.z += a1.x + b1.x;
        na.w += a1.y + b1.y;
    }
    if (j < k) {
        const int s0 = __ldg(src + o + j);
        const uint2 v0 = *(const uint2*)(y + (size_t)s0 * 64 + lane * 2);
        float2 a0 = __half22float2(*(const __half2*)&v0.x);
        float2 a1 = __half22float2(*(const __half2*)&v0.y);
        na.x += a0.x; na.y += a0.y; na.z += a1.x; na.w += a1.y;
    }
    return na;
}

__global__ void agg_kernel(const __half2* __restrict__ y,
                           const int* __restrict__ offs,
                           const int* __restrict__ cnt,
                           const int* __restrict__ src,
                           const float* __restrict__ dis,
                           float* __restrict__ agg, int Nn, int obase) {
    const int c = blockIdx.x * 8 + (threadIdx.x >> 5);
    if (c >= Nn) return;
    const int lane = threadIdx.x & 31;

    float4 acc = ((const float4*)agg)[(size_t)c * 32 + lane];
    const int o = __ldg(offs + obase + c);
    const int k = __ldg(cnt + obase + c);
    const float dc = __ldg(dis + c);
    float4 na = gather_sum(y, src, o, k, lane);
    acc.x += dc * na.x; acc.y += dc * na.y;
    acc.z += dc * na.z; acc.w += dc * na.w;
    ((float4*)agg)[(size_t)c * 32 + lane] = acc;
}

// ---------------------------------------------------------------------------
// CSR gather-aggregate (pass B) + LayerNorm + LeakyReLU + residual.
// hnext[c*hstride + hofs + :] = leaky(LN(init+dis*sum)*g+b) + hprev[c]
// optional aux (stride 512, offset aofs) for JK output slices.
// ---------------------------------------------------------------------------
__global__ void agg_ln_kernel(const float* __restrict__ init,
                              const __half2* __restrict__ y,
                              const int* __restrict__ offs,
                              const int* __restrict__ cnt,
                              const int* __restrict__ src,
                              const float* __restrict__ dis,
                              const float* __restrict__ g,
                              const float* __restrict__ b,
                              const float* __restrict__ hprev,
                              float* __restrict__ hnext, int hstride, int hofs,
                              float* __restrict__ aux, int aofs, int rows_aux,
                              int Nn, int obase) {
    const int c = blockIdx.x * 8 + (threadIdx.x >> 5);
    if (c >= Nn) return;
    const int lane = threadIdx.x & 31;

    float4 acc = ((const float4*)init)[(size_t)c * 32 + lane];
    const int o = __ldg(offs + obase + c);
    const int k = __ldg(cnt + obase + c);
    const float dc = __ldg(dis + c);
    float4 na = gather_sum(y, src, o, k, lane);
    acc.x += dc * na.x; acc.y += dc * na.y;
    acc.z += dc * na.z; acc.w += dc * na.w;

    float s1 = acc.x + acc.y + acc.z + acc.w;
#pragma unroll
    for (int off = 16; off > 0; off >>= 1) s1 += __shfl_xor_sync(0xffffffffu, s1, off);
    const float mu = s1 * (1.0f / 128.0f);
    float dx = acc.x - mu, dy = acc.y - mu, dz = acc.z - mu, dw = acc.w - mu;
    float q = dx * dx + dy * dy + dz * dz + dw * dw;
#pragma unroll
    for (int off = 16; off > 0; off >>= 1) q += __shfl_xor_sync(0xffffffffu, q, off);
    const float rstd = rsqrtf(q * (1.0f / 128.0f) + LN_EPS);

    float4 gg = ((const float4*)g)[lane];
    float4 bb = ((const float4*)b)[lane];
    float4 hp = ((const float4*)hprev)[(size_t)c * 32 + lane];
    float4 out;
    out.x = leaky(dx * rstd * gg.x + bb.x) + hp.x;
    out.y = leaky(dy * rstd * gg.y + bb.y) + hp.y;
    out.z = leaky(dz * rstd * gg.z + bb.z) + hp.z;
    out.w = leaky(dw * rstd * gg.w + bb.w) + hp.w;
    ((float4*)(hnext + (size_t)c * hstride + hofs))[lane] = out;
    if (aux && c < rows_aux)
        ((float4*)(aux + (size_t)c * 512 + aofs))[lane] = out;
}

// ---------------------------------------------------------------------------
// Launch
// ---------------------------------------------------------------------------
extern "C" void kernel_launch(void* const* d_in, const int* in_sizes, int n_in,
                              void* d_out, int out_size) {
    const float* x        = (const float*)d_in[0];
    const float* enc_w1   = (const float*)d_in[1];
    const float* enc_b1   = (const float*)d_in[2];
    const float* enc_w2   = (const float*)d_in[3];
    const float* enc_b2   = (const float*)d_in[4];
    const float* conv_w   = (const float*)d_in[5];
    const float* conv_b   = (const float*)d_in[6];
    const float* conv_rt  = (const float*)d_in[7];
    const float* reconv_w = (const float*)d_in[8];
    const float* reconv_b = (const float*)d_in[9];
    const float* reconv_rt= (const float*)d_in[10];
    const float* ln_g     = (const float*)d_in[11];
    const float* ln_b     = (const float*)d_in[12];
    const int*   eA       = (const int*)d_in[13];
    const int*   eB       = (const int*)d_in[14];

    const int N  = in_sizes[0] / 32;
    const int Ea = in_sizes[13] / 2;
    const int Eb = in_sizes[14] / 2;
    const int rows_out = out_size / 512;

    const int* rowsA = eA; const int* colsA = eA + Ea;
    const int* rowsB = eB; const int* colsB = eB + Eb;

    void* p;
    cudaGetSymbolAddress(&p, g_H);    float* H    = (float*)p;
    cudaGetSymbolAddress(&p, g_XL);   float* XL   = (float*)p;
    cudaGetSymbolAddress(&p, g_AGG);  float* AGG  = (float*)p;
    cudaGetSymbolAddress(&p, g_H1);   float* H1E  = (float*)p;
    cudaGetSymbolAddress(&p, g_Y);    __half2* Y  = (__half2*)p;
    cudaGetSymbolAddress(&p, g_disA); float* disA = (float*)p;
    cudaGetSymbolAddress(&p, g_disB); float* disB = (float*)p;
    cudaGetSymbolAddress(&p, g_invA); float* invA = (float*)p;
    cudaGetSymbolAddress(&p, g_invB); float* invB = (float*)p;
    cudaGetSymbolAddress(&p, g_icsr); int* icsr   = (int*)p;
    cudaGetSymbolAddress(&p, g_offs); int* offs   = (int*)p;
    cudaGetSymbolAddress(&p, g_src);  int* src    = (int*)p;
    cudaGetSymbolAddress(&p, g_bsums);int* bsums  = (int*)p;
    cudaGetSymbolAddress(&p, g_Bhi);  __nv_bfloat16* BH = (__nv_bfloat16*)p;
    cudaGetSymbolAddress(&p, g_Blo);  __nv_bfloat16* BL = (__nv_bfloat16*)p;

    int* rowcntA = icsr;
    int* rowcntB = icsr + NMAX;
    int* colcnt  = icsr + 2 * NMAX;
    int* cursor  = icsr + 4 * NMAX;

    const size_t hstride = (size_t)NMAX * EMB;
    float* dout = (float*)d_out;

    cudaFuncSetAttribute(gemm_tc_kernel,
                         cudaFuncAttributeMaxDynamicSharedMemorySize, SMEM_TC);

    // ---- weight prep ----
    prep_all_kernel<<<18 * 32, 256>>>(enc_w1, enc_w2, conv_w, reconv_w, BH, BL);

    // ---- CSR build + degrees ----
    zero_kernel<<<(6 * NMAX + 255) / 256, 256>>>(icsr, 6 * NMAX);
    hist2_kernel<<<(Ea + 255) / 256, 256>>>(rowsA, colsA, rowcntA, colcnt, Ea);
    hist2_kernel<<<(Eb + 255) / 256, 256>>>(rowsB, colsB, rowcntB, colcnt + NMAX, Eb);
    deg_fin_kernel<<<(N + 255) / 256, 256>>>(rowcntA, disA, invA, N);
    deg_fin_kernel<<<(N + 255) / 256, 256>>>(rowcntB, disB, invB, N);
    {
        const int n2 = 2 * NMAX;
        const int nb = (n2 + 1023) / 1024;
        scan_block_kernel<<<nb, 256>>>(colcnt, offs, bsums, n2);
        scan_sums_kernel<<<1, 512>>>(bsums, nb);
        scan_add_kernel<<<(n2 + 255) / 256, 256>>>(offs, bsums, n2);
    }
    fill_kernel<<<(Ea + 255) / 256, 256>>>(rowsA, colsA, offs, cursor, src, Ea, 0);
    fill_kernel<<<(Eb + 255) / 256, 256>>>(rowsB, colsB, offs, cursor, src, Eb, NMAX);

    const int tiles = (N + 127) / 128;

    // ---- encoder ----
    gemm_tc_kernel<<<tiles, 256, SMEM_TC>>>(x, 32, N,
        BH + 0 * 8192, BL + 0 * 8192, 1, 32, enc_b1, H1E, 256, 0, 1,
        nullptr, 0, 0, 0, nullptr, nullptr, nullptr, nullptr);
    gemm_tc_kernel<<<tiles, 256, SMEM_TC>>>(x, 32, N,
        BH + 1 * 8192, BL + 1 * 8192, 1, 32, enc_b1 + 128, H1E, 256, 128, 1,
        nullptr, 0, 0, 0, nullptr, nullptr, nullptr, nullptr);
    // enc2 -> H0, JK slice 0 of d_out
    gemm_tc_kernel<<<tiles, 256, SMEM_TC>>>(H1E, 256, N,
        BH + 2 * 8192, BL + 2 * 8192, 4, 256, enc_b2, H, 128, 0, 1,
        dout, 0, rows_out, 0, nullptr, nullptr, nullptr, nullptr);

    // ---- GCN layers ----
    for (int l = 0; l < 3; l++) {
        const float* hl = H + (size_t)l * hstride;
        float* hn = H + (size_t)(l + 1) * hstride;
        const int last = (l == 2);

        // conv (edge set A): GEMM writes init->AGG + y; agg in-place on AGG
        gemm_tc_kernel<<<tiles, 256, SMEM_TC>>>(hl, 128, N,
            BH + (6 + 2 * l) * 8192, BL + (6 + 2 * l) * 8192, 2, 128,
            conv_b + l * EMB, AGG, 128, 0, 0,
            nullptr, 0, 0, 1, conv_rt + l * EMB, disA, invA, Y);
        agg_kernel<<<(N + 7) / 8, 256>>>(Y, offs, colcnt, src, disA, AGG, N, 0);

        // reconv (edge set B): GEMM writes init->XL + y; agg+LN+residual
        gemm_tc_kernel<<<tiles, 256, SMEM_TC>>>(AGG, 128, N,
            BH + (12 + 2 * l) * 8192, BL + (12 + 2 * l) * 8192, 2, 128,
            reconv_b + l * EMB, XL, 128, 0, 0,
            nullptr, 0, 0, 1, reconv_rt + l * EMB, disB, invB, Y);
        if (!last) {
            agg_ln_kernel<<<(N + 7) / 8, 256>>>(XL, Y, offs, colcnt, src, disB,
                ln_g + l * EMB, ln_b + l * EMB, hl,
                hn, 128, 0, dout, (l + 1) * 128, rows_out, N, NMAX);
        } else {
            // h3 only feeds the output: compute only the first rows_out nodes,
            // write directly into the JK slice of d_out.
            agg_ln_kernel<<<(rows_out + 7) / 8, 256>>>(XL, Y, offs, colcnt, src, disB,
                ln_g + l * EMB, ln_b + l * EMB, hl,
                dout, 512, 384, nullptr, 0, 0, rows_out, NMAX);
        }
    }
}